// round 15
// baseline (speedup 1.0000x reference)
#include <cuda_runtime.h>
#include <stdint.h>

#define NMAX 100000
#define EMAX 1600000
#define CH 128

// ---------------- scratch (device globals; no allocations allowed) ----------
__device__ float g_deg[NMAX];
__device__ float g_dinv[NMAX];
__device__ int   g_cnt[NMAX];
__device__ int   g_off[NMAX + 1];
__device__ int   g_pos[NMAX];
__device__ int   g_bsum[128];
__device__ int   g_boff[128];
__device__ __align__(16) int2  g_epack[EMAX];     // (src, coef bits)
__device__ __align__(16) float g_bufA[(size_t)NMAX * CH];
__device__ __align__(16) float g_bufB[(size_t)NMAX * CH];

// ---------------- graph preprocessing ---------------------------------------

__global__ void init_kernel(int n) {
    int i = blockIdx.x * blockDim.x + threadIdx.x;
    if (i < n) {
        g_deg[i] = 1.0f;   // self-loop weight 1
        g_cnt[i] = 0;
    }
}

__global__ void deg_cnt_kernel(const int* __restrict__ row,
                               const int* __restrict__ col,
                               const float* __restrict__ ew, int E) {
    int e = blockIdx.x * blockDim.x + threadIdx.x;
    if (e < E) {
        int c = col[e];
        atomicAdd(&g_deg[c], ew[e]);
        atomicAdd(&g_cnt[c], 1);
    }
}

// phase 1: per-block sums of g_cnt (1024 elems per block)
__global__ void __launch_bounds__(1024)
block_sum_kernel(int n) {
    __shared__ int wred[32];
    int i = blockIdx.x * 1024 + threadIdx.x;
    int v = (i < n) ? g_cnt[i] : 0;
    #pragma unroll
    for (int d = 16; d; d >>= 1) v += __shfl_down_sync(0xffffffffu, v, d);
    if ((threadIdx.x & 31) == 0) wred[threadIdx.x >> 5] = v;
    __syncthreads();
    if (threadIdx.x < 32) {
        int s = wred[threadIdx.x];
        #pragma unroll
        for (int d = 16; d; d >>= 1) s += __shfl_down_sync(0xffffffffu, s, d);
        if (threadIdx.x == 0) g_bsum[blockIdx.x] = s;
    }
}

// phase 2: exclusive scan of the block sums (single warp, chunked)
__global__ void scan_bsum_kernel(int nb, int n) {
    int lane = threadIdx.x;
    int carry = 0;
    for (int base = 0; base < nb; base += 32) {
        int i = base + lane;
        int v = (i < nb) ? g_bsum[i] : 0;
        int x = v;
        #pragma unroll
        for (int d = 1; d < 32; d <<= 1) {
            int y = __shfl_up_sync(0xffffffffu, x, d);
            if (lane >= d) x += y;
        }
        if (i < nb) g_boff[i] = x - v + carry;
        int tot = __shfl_sync(0xffffffffu, x, 31);
        carry += tot;
    }
    if (lane == 0) g_off[n] = carry;
}

// phase 3: block-local exclusive scan + block offset; also compute dinv
__global__ void __launch_bounds__(1024)
scan_final_kernel(int n) {
    __shared__ int wsum[32];
    int tid = threadIdx.x;
    int lane = tid & 31, wid = tid >> 5;
    int i = blockIdx.x * 1024 + tid;
    int v = (i < n) ? g_cnt[i] : 0;
    int x = v;
    #pragma unroll
    for (int d = 1; d < 32; d <<= 1) {
        int y = __shfl_up_sync(0xffffffffu, x, d);
        if (lane >= d) x += y;
    }
    if (lane == 31) wsum[wid] = x;
    __syncthreads();
    if (tid < 32) {
        int w = wsum[tid];
        int xs = w;
        #pragma unroll
        for (int d = 1; d < 32; d <<= 1) {
            int y = __shfl_up_sync(0xffffffffu, xs, d);
            if (tid >= d) xs += y;
        }
        wsum[tid] = xs - w;   // exclusive warp offsets
    }
    __syncthreads();
    if (i < n) {
        int excl = x - v + wsum[wid] + g_boff[blockIdx.x];
        g_off[i] = excl;
        g_pos[i] = excl;
        float dg = g_deg[i];
        g_dinv[i] = (dg > 0.0f) ? rsqrtf(dg) : 0.0f;
    }
}

__global__ void fill_kernel(const int* __restrict__ row,
                            const int* __restrict__ col,
                            const float* __restrict__ ew, int E) {
    int e = blockIdx.x * blockDim.x + threadIdx.x;
    if (e < E) {
        int r = row[e], c = col[e];
        int p = atomicAdd(&g_pos[c], 1);
        float cf = g_dinv[r] * ew[e] * g_dinv[c];
        g_epack[p] = make_int2(r, __float_as_int(cf));
    }
}

// ---------------- TF32 tensor-core GEMM --------------------------------------
// C[M,128] = A[M,128] @ W[128,128], 3xTF32 split for ~fp32 precision.
// CTA: 128x128, K in 2 chunks of 64. 8 warps, warp tile 32x64.
// mma.sync.aligned.m16n8k8.row.col.f32.tf32.tf32.f32

#define BK 64
#define A_STRIDE 68       // BK + 4 pad (conflict-free)
#define B_STRIDE 132      // 128 + 4 pad
#define SM_AH 0
#define SM_AL (128 * A_STRIDE)
#define SM_BH (2 * 128 * A_STRIDE)
#define SM_BL (2 * 128 * A_STRIDE + BK * B_STRIDE)
#define SMEM_FLOATS (2 * 128 * A_STRIDE + 2 * BK * B_STRIDE)
#define SMEM_BYTES (SMEM_FLOATS * 4)

__device__ __forceinline__ uint32_t cvt_tf32(float v) {
    uint32_t u;
    asm("cvt.rna.tf32.f32 %0, %1;" : "=r"(u) : "f"(v));
    return u;
}

__device__ __forceinline__ void mma_tf32(float* c, const uint32_t* a,
                                         uint32_t b0, uint32_t b1) {
    asm("mma.sync.aligned.m16n8k8.row.col.f32.tf32.tf32.f32 "
        "{%0,%1,%2,%3}, {%4,%5,%6,%7}, {%8,%9}, {%0,%1,%2,%3};"
        : "+f"(c[0]), "+f"(c[1]), "+f"(c[2]), "+f"(c[3])
        : "r"(a[0]), "r"(a[1]), "r"(a[2]), "r"(a[3]), "r"(b0), "r"(b1));
}

__global__ void __launch_bounds__(256)
gemm_tf32_kernel(const float* __restrict__ Aext, int src_sel, int dst_sel,
                 const float* __restrict__ W, int M) {
    const float* A = (src_sel == 0) ? Aext : (src_sel == 1 ? g_bufA : g_bufB);
    float* Cout = (dst_sel == 1) ? g_bufA : g_bufB;

    extern __shared__ float smem[];
    float* sAh = smem + SM_AH;
    float* sAl = smem + SM_AL;
    float* sBh = smem + SM_BH;
    float* sBl = smem + SM_BL;
    const uint32_t* uAh = (const uint32_t*)sAh;
    const uint32_t* uAl = (const uint32_t*)sAl;
    const uint32_t* uBh = (const uint32_t*)sBh;
    const uint32_t* uBl = (const uint32_t*)sBl;

    int tid = threadIdx.x;
    int wid = tid >> 5, lane = tid & 31;
    int g = lane >> 2, tig = lane & 3;
    int m_off = (wid & 3) * 32;
    int n_off = (wid >> 2) * 64;
    int brow = blockIdx.x * 128;

    float c[2][8][4];
    #pragma unroll
    for (int mt = 0; mt < 2; mt++)
        #pragma unroll
        for (int nt = 0; nt < 8; nt++)
            #pragma unroll
            for (int j = 0; j < 4; j++) c[mt][nt][j] = 0.0f;

    #pragma unroll
    for (int ck = 0; ck < 2; ck++) {
        int kbase = ck * BK;
        // stage A chunk [128 x 64] -> split hi/lo
        #pragma unroll
        for (int i = 0; i < 8; i++) {
            int idx = i * 256 + tid;
            int r = idx >> 4;            // 16 float4 per row
            int c4 = (idx & 15) * 4;
            int gr = brow + r;
            float4 v = make_float4(0.f, 0.f, 0.f, 0.f);
            if (gr < M) v = *(const float4*)(A + (size_t)gr * 128 + kbase + c4);
            float4 h, l;
            h.x = __uint_as_float(cvt_tf32(v.x)); l.x = __uint_as_float(cvt_tf32(v.x - h.x));
            h.y = __uint_as_float(cvt_tf32(v.y)); l.y = __uint_as_float(cvt_tf32(v.y - h.y));
            h.z = __uint_as_float(cvt_tf32(v.z)); l.z = __uint_as_float(cvt_tf32(v.z - h.z));
            h.w = __uint_as_float(cvt_tf32(v.w)); l.w = __uint_as_float(cvt_tf32(v.w - h.w));
            *(float4*)&sAh[r * A_STRIDE + c4] = h;
            *(float4*)&sAl[r * A_STRIDE + c4] = l;
        }
        // stage W chunk [64 x 128] -> split hi/lo
        #pragma unroll
        for (int i = 0; i < 8; i++) {
            int idx = i * 256 + tid;
            int r = idx >> 5;            // 32 float4 per row
            int c4 = (idx & 31) * 4;
            float4 v = *(const float4*)(W + (size_t)(kbase + r) * 128 + c4);
            float4 h, l;
            h.x = __uint_as_float(cvt_tf32(v.x)); l.x = __uint_as_float(cvt_tf32(v.x - h.x));
            h.y = __uint_as_float(cvt_tf32(v.y)); l.y = __uint_as_float(cvt_tf32(v.y - h.y));
            h.z = __uint_as_float(cvt_tf32(v.z)); l.z = __uint_as_float(cvt_tf32(v.z - h.z));
            h.w = __uint_as_float(cvt_tf32(v.w)); l.w = __uint_as_float(cvt_tf32(v.w - h.w));
            *(float4*)&sBh[r * B_STRIDE + c4] = h;
            *(float4*)&sBl[r * B_STRIDE + c4] = l;
        }
        __syncthreads();

        #pragma unroll
        for (int ks = 0; ks < BK / 8; ks++) {
            int kk = ks * 8;
            uint32_t ah[2][4], al[2][4];
            #pragma unroll
            for (int mt = 0; mt < 2; mt++) {
                int rb = m_off + mt * 16 + g;
                int o0 = rb * A_STRIDE + kk + tig;
                int o1 = (rb + 8) * A_STRIDE + kk + tig;
                ah[mt][0] = uAh[o0];     ah[mt][1] = uAh[o1];
                ah[mt][2] = uAh[o0 + 4]; ah[mt][3] = uAh[o1 + 4];
                al[mt][0] = uAl[o0];     al[mt][1] = uAl[o1];
                al[mt][2] = uAl[o0 + 4]; al[mt][3] = uAl[o1 + 4];
            }
            uint32_t bh[8][2], bl[8][2];
            #pragma unroll
            for (int nt = 0; nt < 8; nt++) {
                int cb = n_off + nt * 8 + g;
                int o0 = (kk + tig) * B_STRIDE + cb;
                int o1 = (kk + tig + 4) * B_STRIDE + cb;
                bh[nt][0] = uBh[o0]; bh[nt][1] = uBh[o1];
                bl[nt][0] = uBl[o0]; bl[nt][1] = uBl[o1];
            }
            #pragma unroll
            for (int mt = 0; mt < 2; mt++)
                #pragma unroll
                for (int nt = 0; nt < 8; nt++) {
                    mma_tf32(c[mt][nt], ah[mt], bh[nt][0], bh[nt][1]);
                    mma_tf32(c[mt][nt], al[mt], bh[nt][0], bh[nt][1]);
                    mma_tf32(c[mt][nt], ah[mt], bl[nt][0], bl[nt][1]);
                }
        }
        __syncthreads();
    }

    // write back
    #pragma unroll
    for (int mt = 0; mt < 2; mt++) {
        #pragma unroll
        for (int nt = 0; nt < 8; nt++) {
            int row0 = brow + m_off + mt * 16 + g;
            int col = n_off + nt * 8 + tig * 2;
            if (row0 < M)
                *(float2*)&Cout[(size_t)row0 * 128 + col] =
                    make_float2(c[mt][nt][0], c[mt][nt][1]);
            int row1 = row0 + 8;
            if (row1 < M)
                *(float2*)&Cout[(size_t)row1 * 128 + col] =
                    make_float2(c[mt][nt][2], c[mt][nt][3]);
        }
    }
}

// ---------------- Aggregation: out[i] = sum coef*xw[nbr] + dinv[i]^2*xw[i] + b
// warp per node; lane owns 4 channels (float4).

__global__ void __launch_bounds__(256)
agg_kernel(int src_sel, const float* __restrict__ bias,
           float* __restrict__ out, int n, int do_relu) {
    const float* xw = (src_sel == 1) ? g_bufA : g_bufB;
    int warp = (blockIdx.x * blockDim.x + threadIdx.x) >> 5;
    int lane = threadIdx.x & 31;
    if (warp >= n) return;
    int i = warp;

    const float4* xw4 = (const float4*)xw;
    float4 b4 = ((const float4*)bias)[lane];
    float di = g_dinv[i];
    float sc = di * di;

    float4 self = __ldg(&xw4[(size_t)i * 32 + lane]);
    float4 acc = make_float4(self.x * sc, self.y * sc, self.z * sc, self.w * sc);

    int s = g_off[i], e = g_off[i + 1];
    for (int j0 = s; j0 < e; j0 += 32) {
        int j = j0 + lane;
        int idx = 0;
        float cf = 0.0f;
        if (j < e) {
            int2 p = __ldg(&g_epack[j]);
            idx = p.x;
            cf = __int_as_float(p.y);
        }
        int m = min(32, e - j0);
        #pragma unroll 4
        for (int t = 0; t < m; ++t) {
            int r = __shfl_sync(0xffffffffu, idx, t);
            float cc = __shfl_sync(0xffffffffu, cf, t);
            float4 v = __ldg(&xw4[(size_t)r * 32 + lane]);
            acc.x = fmaf(cc, v.x, acc.x);
            acc.y = fmaf(cc, v.y, acc.y);
            acc.z = fmaf(cc, v.z, acc.z);
            acc.w = fmaf(cc, v.w, acc.w);
        }
    }

    acc.x += b4.x; acc.y += b4.y; acc.z += b4.z; acc.w += b4.w;
    if (do_relu) {
        acc.x = fmaxf(acc.x, 0.0f);
        acc.y = fmaxf(acc.y, 0.0f);
        acc.z = fmaxf(acc.z, 0.0f);
        acc.w = fmaxf(acc.w, 0.0f);
    }
    ((float4*)out)[(size_t)i * 32 + lane] = acc;
}

// ---------------- launch ------------------------------------------------------

extern "C" void kernel_launch(void* const* d_in, const int* in_sizes, int n_in,
                              void* d_out, int out_size) {
    const float* x   = (const float*)d_in[0];
    const int*   ei  = (const int*)d_in[1];
    const float* ew  = (const float*)d_in[2];
    const float* W1  = (const float*)d_in[3];
    const float* b1  = (const float*)d_in[4];
    const float* W2  = (const float*)d_in[5];
    const float* b2  = (const float*)d_in[6];
    const float* W3  = (const float*)d_in[7];
    const float* b3  = (const float*)d_in[8];
    float* out = (float*)d_out;

    int n = in_sizes[0] / CH;        // 100000
    int E = in_sizes[2];             // 1600000
    const int* row = ei;
    const int* col = ei + E;

    float* bufB = nullptr;
    cudaGetSymbolAddress((void**)&bufB, g_bufB);

    cudaFuncSetAttribute(gemm_tf32_kernel,
                         cudaFuncAttributeMaxDynamicSharedMemorySize, SMEM_BYTES);

    int tb = 256;
    int gn = (n + tb - 1) / tb;
    int ge = (E + tb - 1) / tb;
    int nb = (n + 1023) / 1024;
    int g_gemm = (n + 127) / 128;
    int g_agg = (n * 32 + tb - 1) / tb;

    // preprocessing: degrees + counts, parallel scan, dinv, CSR fill
    init_kernel<<<gn, tb>>>(n);
    deg_cnt_kernel<<<ge, tb>>>(row, col, ew, E);
    block_sum_kernel<<<nb, 1024>>>(n);
    scan_bsum_kernel<<<1, 32>>>(nb, n);
    scan_final_kernel<<<nb, 1024>>>(n);
    fill_kernel<<<ge, tb>>>(row, col, ew, E);

    // layer 1: bufA = x@W1 ; bufB = relu(Agg(bufA)+b1)
    gemm_tf32_kernel<<<g_gemm, tb, SMEM_BYTES>>>(x, 0, 1, W1, n);
    agg_kernel<<<g_agg, tb>>>(1, b1, bufB, n, 1);

    // layer 2: bufA = bufB@W2 ; bufB = relu(Agg(bufA)+b2)
    gemm_tf32_kernel<<<g_gemm, tb, SMEM_BYTES>>>(nullptr, 2, 1, W2, n);
    agg_kernel<<<g_agg, tb>>>(1, b2, bufB, n, 1);

    // layer 3: bufA = bufB@W3 ; out = Agg(bufA)+b3
    gemm_tf32_kernel<<<g_gemm, tb, SMEM_BYTES>>>(nullptr, 2, 1, W3, n);
    agg_kernel<<<g_agg, tb>>>(1, b3, out, n, 0);
}

// round 16
// speedup vs baseline: 1.0042x; 1.0042x over previous
#include <cuda_runtime.h>
#include <stdint.h>

#define NMAX 100000
#define EMAX 1600000
#define CH 128

// ---------------- scratch (device globals; no allocations allowed) ----------
__device__ float g_deg[NMAX];
__device__ float g_dinv[NMAX];
__device__ int   g_cnt[NMAX];
__device__ int   g_off[NMAX + 1];
__device__ int   g_pos[NMAX];
__device__ int   g_bsum[128];
__device__ int   g_boff[128];
__device__ __align__(16) int2  g_epack[EMAX];     // (src, coef bits)
__device__ __align__(16) float g_bufA[(size_t)NMAX * CH];
__device__ __align__(16) float g_bufB[(size_t)NMAX * CH];

// ---------------- graph preprocessing ---------------------------------------

__global__ void init_kernel(int n) {
    int i = blockIdx.x * blockDim.x + threadIdx.x;
    if (i < n) {
        g_deg[i] = 1.0f;   // self-loop weight 1
        g_cnt[i] = 0;
    }
}

__global__ void deg_cnt_kernel(const int* __restrict__ row,
                               const int* __restrict__ col,
                               const float* __restrict__ ew, int E) {
    int e = blockIdx.x * blockDim.x + threadIdx.x;
    if (e < E) {
        int c = col[e];
        atomicAdd(&g_deg[c], ew[e]);
        atomicAdd(&g_cnt[c], 1);
    }
}

// phase 1: per-block sums of g_cnt (1024 elems per block)
__global__ void __launch_bounds__(1024)
block_sum_kernel(int n) {
    __shared__ int wred[32];
    int i = blockIdx.x * 1024 + threadIdx.x;
    int v = (i < n) ? g_cnt[i] : 0;
    #pragma unroll
    for (int d = 16; d; d >>= 1) v += __shfl_down_sync(0xffffffffu, v, d);
    if ((threadIdx.x & 31) == 0) wred[threadIdx.x >> 5] = v;
    __syncthreads();
    if (threadIdx.x < 32) {
        int s = wred[threadIdx.x];
        #pragma unroll
        for (int d = 16; d; d >>= 1) s += __shfl_down_sync(0xffffffffu, s, d);
        if (threadIdx.x == 0) g_bsum[blockIdx.x] = s;
    }
}

// phase 2: exclusive scan of the block sums (single warp, chunked)
__global__ void scan_bsum_kernel(int nb, int n) {
    int lane = threadIdx.x;
    int carry = 0;
    for (int base = 0; base < nb; base += 32) {
        int i = base + lane;
        int v = (i < nb) ? g_bsum[i] : 0;
        int x = v;
        #pragma unroll
        for (int d = 1; d < 32; d <<= 1) {
            int y = __shfl_up_sync(0xffffffffu, x, d);
            if (lane >= d) x += y;
        }
        if (i < nb) g_boff[i] = x - v + carry;
        int tot = __shfl_sync(0xffffffffu, x, 31);
        carry += tot;
    }
    if (lane == 0) g_off[n] = carry;
}

// phase 3: block-local exclusive scan + block offset; also compute dinv
__global__ void __launch_bounds__(1024)
scan_final_kernel(int n) {
    __shared__ int wsum[32];
    int tid = threadIdx.x;
    int lane = tid & 31, wid = tid >> 5;
    int i = blockIdx.x * 1024 + tid;
    int v = (i < n) ? g_cnt[i] : 0;
    int x = v;
    #pragma unroll
    for (int d = 1; d < 32; d <<= 1) {
        int y = __shfl_up_sync(0xffffffffu, x, d);
        if (lane >= d) x += y;
    }
    if (lane == 31) wsum[wid] = x;
    __syncthreads();
    if (tid < 32) {
        int w = wsum[tid];
        int xs = w;
        #pragma unroll
        for (int d = 1; d < 32; d <<= 1) {
            int y = __shfl_up_sync(0xffffffffu, xs, d);
            if (tid >= d) xs += y;
        }
        wsum[tid] = xs - w;   // exclusive warp offsets
    }
    __syncthreads();
    if (i < n) {
        int excl = x - v + wsum[wid] + g_boff[blockIdx.x];
        g_off[i] = excl;
        g_pos[i] = excl;
        float dg = g_deg[i];
        g_dinv[i] = (dg > 0.0f) ? rsqrtf(dg) : 0.0f;
    }
}

__global__ void fill_kernel(const int* __restrict__ row,
                            const int* __restrict__ col,
                            const float* __restrict__ ew, int E) {
    int e = blockIdx.x * blockDim.x + threadIdx.x;
    if (e < E) {
        int r = row[e], c = col[e];
        int p = atomicAdd(&g_pos[c], 1);
        float cf = g_dinv[r] * ew[e] * g_dinv[c];
        g_epack[p] = make_int2(r, __float_as_int(cf));
    }
}

// ---------------- TF32 tensor-core GEMM --------------------------------------
// C[M,128] = A[M,128] @ W[128,128], 3xTF32 split for ~fp32 precision.
// CTA: 128x128, K in 2 chunks of 64. 8 warps, warp tile 32x64.
// mma.sync.aligned.m16n8k8.row.col.f32.tf32.tf32.f32

#define BK 64
#define A_STRIDE 68       // BK + 4 pad (conflict-free)
#define B_STRIDE 132      // 128 + 4 pad
#define SM_AH 0
#define SM_AL (128 * A_STRIDE)
#define SM_BH (2 * 128 * A_STRIDE)
#define SM_BL (2 * 128 * A_STRIDE + BK * B_STRIDE)
#define SMEM_FLOATS (2 * 128 * A_STRIDE + 2 * BK * B_STRIDE)
#define SMEM_BYTES (SMEM_FLOATS * 4)

__device__ __forceinline__ uint32_t cvt_tf32(float v) {
    uint32_t u;
    asm("cvt.rna.tf32.f32 %0, %1;" : "=r"(u) : "f"(v));
    return u;
}

__device__ __forceinline__ void mma_tf32(float* c, const uint32_t* a,
                                         uint32_t b0, uint32_t b1) {
    asm("mma.sync.aligned.m16n8k8.row.col.f32.tf32.tf32.f32 "
        "{%0,%1,%2,%3}, {%4,%5,%6,%7}, {%8,%9}, {%0,%1,%2,%3};"
        : "+f"(c[0]), "+f"(c[1]), "+f"(c[2]), "+f"(c[3])
        : "r"(a[0]), "r"(a[1]), "r"(a[2]), "r"(a[3]), "r"(b0), "r"(b1));
}

__global__ void __launch_bounds__(256)
gemm_tf32_kernel(const float* __restrict__ Aext, int src_sel, int dst_sel,
                 const float* __restrict__ W, int M) {
    const float* A = (src_sel == 0) ? Aext : (src_sel == 1 ? g_bufA : g_bufB);
    float* Cout = (dst_sel == 1) ? g_bufA : g_bufB;

    extern __shared__ float smem[];
    float* sAh = smem + SM_AH;
    float* sAl = smem + SM_AL;
    float* sBh = smem + SM_BH;
    float* sBl = smem + SM_BL;
    const uint32_t* uAh = (const uint32_t*)sAh;
    const uint32_t* uAl = (const uint32_t*)sAl;
    const uint32_t* uBh = (const uint32_t*)sBh;
    const uint32_t* uBl = (const uint32_t*)sBl;

    int tid = threadIdx.x;
    int wid = tid >> 5, lane = tid & 31;
    int g = lane >> 2, tig = lane & 3;
    int m_off = (wid & 3) * 32;
    int n_off = (wid >> 2) * 64;
    int brow = blockIdx.x * 128;

    float c[2][8][4];
    #pragma unroll
    for (int mt = 0; mt < 2; mt++)
        #pragma unroll
        for (int nt = 0; nt < 8; nt++)
            #pragma unroll
            for (int j = 0; j < 4; j++) c[mt][nt][j] = 0.0f;

    #pragma unroll
    for (int ck = 0; ck < 2; ck++) {
        int kbase = ck * BK;
        // stage A chunk [128 x 64] -> split hi/lo
        #pragma unroll
        for (int i = 0; i < 8; i++) {
            int idx = i * 256 + tid;
            int r = idx >> 4;            // 16 float4 per row
            int c4 = (idx & 15) * 4;
            int gr = brow + r;
            float4 v = make_float4(0.f, 0.f, 0.f, 0.f);
            if (gr < M) v = *(const float4*)(A + (size_t)gr * 128 + kbase + c4);
            float4 h, l;
            h.x = __uint_as_float(cvt_tf32(v.x)); l.x = __uint_as_float(cvt_tf32(v.x - h.x));
            h.y = __uint_as_float(cvt_tf32(v.y)); l.y = __uint_as_float(cvt_tf32(v.y - h.y));
            h.z = __uint_as_float(cvt_tf32(v.z)); l.z = __uint_as_float(cvt_tf32(v.z - h.z));
            h.w = __uint_as_float(cvt_tf32(v.w)); l.w = __uint_as_float(cvt_tf32(v.w - h.w));
            *(float4*)&sAh[r * A_STRIDE + c4] = h;
            *(float4*)&sAl[r * A_STRIDE + c4] = l;
        }
        // stage W chunk [64 x 128] -> split hi/lo
        #pragma unroll
        for (int i = 0; i < 8; i++) {
            int idx = i * 256 + tid;
            int r = idx >> 5;            // 32 float4 per row
            int c4 = (idx & 31) * 4;
            float4 v = *(const float4*)(W + (size_t)(kbase + r) * 128 + c4);
            float4 h, l;
            h.x = __uint_as_float(cvt_tf32(v.x)); l.x = __uint_as_float(cvt_tf32(v.x - h.x));
            h.y = __uint_as_float(cvt_tf32(v.y)); l.y = __uint_as_float(cvt_tf32(v.y - h.y));
            h.z = __uint_as_float(cvt_tf32(v.z)); l.z = __uint_as_float(cvt_tf32(v.z - h.z));
            h.w = __uint_as_float(cvt_tf32(v.w)); l.w = __uint_as_float(cvt_tf32(v.w - h.w));
            *(float4*)&sBh[r * B_STRIDE + c4] = h;
            *(float4*)&sBl[r * B_STRIDE + c4] = l;
        }
        __syncthreads();

        #pragma unroll
        for (int ks = 0; ks < BK / 8; ks++) {
            int kk = ks * 8;
            uint32_t ah[2][4], al[2][4];
            #pragma unroll
            for (int mt = 0; mt < 2; mt++) {
                int rb = m_off + mt * 16 + g;
                int o0 = rb * A_STRIDE + kk + tig;
                int o1 = (rb + 8) * A_STRIDE + kk + tig;
                ah[mt][0] = uAh[o0];     ah[mt][1] = uAh[o1];
                ah[mt][2] = uAh[o0 + 4]; ah[mt][3] = uAh[o1 + 4];
                al[mt][0] = uAl[o0];     al[mt][1] = uAl[o1];
                al[mt][2] = uAl[o0 + 4]; al[mt][3] = uAl[o1 + 4];
            }
            uint32_t bh[8][2], bl[8][2];
            #pragma unroll
            for (int nt = 0; nt < 8; nt++) {
                int cb = n_off + nt * 8 + g;
                int o0 = (kk + tig) * B_STRIDE + cb;
                int o1 = (kk + tig + 4) * B_STRIDE + cb;
                bh[nt][0] = uBh[o0]; bh[nt][1] = uBh[o1];
                bl[nt][0] = uBl[o0]; bl[nt][1] = uBl[o1];
            }
            #pragma unroll
            for (int mt = 0; mt < 2; mt++)
                #pragma unroll
                for (int nt = 0; nt < 8; nt++) {
                    mma_tf32(c[mt][nt], ah[mt], bh[nt][0], bh[nt][1]);
                    mma_tf32(c[mt][nt], al[mt], bh[nt][0], bh[nt][1]);
                    mma_tf32(c[mt][nt], ah[mt], bl[nt][0], bl[nt][1]);
                }
        }
        __syncthreads();
    }

    // write back
    #pragma unroll
    for (int mt = 0; mt < 2; mt++) {
        #pragma unroll
        for (int nt = 0; nt < 8; nt++) {
            int row0 = brow + m_off + mt * 16 + g;
            int col = n_off + nt * 8 + tig * 2;
            if (row0 < M)
                *(float2*)&Cout[(size_t)row0 * 128 + col] =
                    make_float2(c[mt][nt][0], c[mt][nt][1]);
            int row1 = row0 + 8;
            if (row1 < M)
                *(float2*)&Cout[(size_t)row1 * 128 + col] =
                    make_float2(c[mt][nt][2], c[mt][nt][3]);
        }
    }
}

// ---------------- Aggregation: out[i] = sum coef*xw[nbr] + dinv[i]^2*xw[i] + b
// warp per node; lane owns 4 channels (float4).

__global__ void __launch_bounds__(256)
agg_kernel(int src_sel, const float* __restrict__ bias,
           float* __restrict__ out, int n, int do_relu) {
    const float* xw = (src_sel == 1) ? g_bufA : g_bufB;
    int warp = (blockIdx.x * blockDim.x + threadIdx.x) >> 5;
    int lane = threadIdx.x & 31;
    if (warp >= n) return;
    int i = warp;

    const float4* xw4 = (const float4*)xw;
    float4 b4 = ((const float4*)bias)[lane];
    float di = g_dinv[i];
    float sc = di * di;

    float4 self = __ldg(&xw4[(size_t)i * 32 + lane]);
    float4 acc = make_float4(self.x * sc, self.y * sc, self.z * sc, self.w * sc);

    int s = g_off[i], e = g_off[i + 1];
    for (int j0 = s; j0 < e; j0 += 32) {
        int j = j0 + lane;
        int idx = 0;
        float cf = 0.0f;
        if (j < e) {
            int2 p = __ldg(&g_epack[j]);
            idx = p.x;
            cf = __int_as_float(p.y);
        }
        int m = min(32, e - j0);
        #pragma unroll 4
        for (int t = 0; t < m; ++t) {
            int r = __shfl_sync(0xffffffffu, idx, t);
            float cc = __shfl_sync(0xffffffffu, cf, t);
            float4 v = __ldg(&xw4[(size_t)r * 32 + lane]);
            acc.x = fmaf(cc, v.x, acc.x);
            acc.y = fmaf(cc, v.y, acc.y);
            acc.z = fmaf(cc, v.z, acc.z);
            acc.w = fmaf(cc, v.w, acc.w);
        }
    }

    acc.x += b4.x; acc.y += b4.y; acc.z += b4.z; acc.w += b4.w;
    if (do_relu) {
        acc.x = fmaxf(acc.x, 0.0f);
        acc.y = fmaxf(acc.y, 0.0f);
        acc.z = fmaxf(acc.z, 0.0f);
        acc.w = fmaxf(acc.w, 0.0f);
    }
    ((float4*)out)[(size_t)i * 32 + lane] = acc;
}

// ---------------- launch ------------------------------------------------------

extern "C" void kernel_launch(void* const* d_in, const int* in_sizes, int n_in,
                              void* d_out, int out_size) {
    const float* x   = (const float*)d_in[0];
    const int*   ei  = (const int*)d_in[1];
    const float* ew  = (const float*)d_in[2];
    const float* W1  = (const float*)d_in[3];
    const float* b1  = (const float*)d_in[4];
    const float* W2  = (const float*)d_in[5];
    const float* b2  = (const float*)d_in[6];
    const float* W3  = (const float*)d_in[7];
    const float* b3  = (const float*)d_in[8];
    float* out = (float*)d_out;

    int n = in_sizes[0] / CH;        // 100000
    int E = in_sizes[2];             // 1600000
    const int* row = ei;
    const int* col = ei + E;

    float* bufB = nullptr;
    cudaGetSymbolAddress((void**)&bufB, g_bufB);

    cudaFuncSetAttribute(gemm_tf32_kernel,
                         cudaFuncAttributeMaxDynamicSharedMemorySize, SMEM_BYTES);

    int tb = 256;
    int gn = (n + tb - 1) / tb;
    int ge = (E + tb - 1) / tb;
    int nb = (n + 1023) / 1024;
    int g_gemm = (n + 127) / 128;
    int g_agg = (n * 32 + tb - 1) / tb;

    // preprocessing: degrees + counts, parallel scan, dinv, CSR fill
    init_kernel<<<gn, tb>>>(n);
    deg_cnt_kernel<<<ge, tb>>>(row, col, ew, E);
    block_sum_kernel<<<nb, 1024>>>(n);
    scan_bsum_kernel<<<1, 32>>>(nb, n);
    scan_final_kernel<<<nb, 1024>>>(n);
    fill_kernel<<<ge, tb>>>(row, col, ew, E);

    // layer 1: bufA = x@W1 ; bufB = relu(Agg(bufA)+b1)
    gemm_tf32_kernel<<<g_gemm, tb, SMEM_BYTES>>>(x, 0, 1, W1, n);
    agg_kernel<<<g_agg, tb>>>(1, b1, bufB, n, 1);

    // layer 2: bufA = bufB@W2 ; bufB = relu(Agg(bufA)+b2)
    gemm_tf32_kernel<<<g_gemm, tb, SMEM_BYTES>>>(nullptr, 2, 1, W2, n);
    agg_kernel<<<g_agg, tb>>>(1, b2, bufB, n, 1);

    // layer 3: bufA = bufB@W3 ; out = Agg(bufA)+b3
    gemm_tf32_kernel<<<g_gemm, tb, SMEM_BYTES>>>(nullptr, 2, 1, W3, n);
    agg_kernel<<<g_agg, tb>>>(1, b3, out, n, 0);
}